// round 12
// baseline (speedup 1.0000x reference)
#include <cuda_runtime.h>

// WaveLetPooling: input (8, 512, 512, 64) fp32 NHWC.
// a = in[:,0::2,0::2,:], b = in[:,0::2,1::2,:], c = in[:,1::2,0::2,:], d = in[:,1::2,1::2,:]
// ll = .5(a+b+c+d); lh = .5(-a+b-c+d); hl = .5(-a-b+c+d); hh = .5(a-b-c+d)
// Output: [ll | lh | hl | hh], each (8, 256, 256, 64), concatenated in d_out.
//
// FINAL — roofline-converged over an 11-round sweep (session closed).
// Pure streaming op: 537 MB read + 537 MB write, zero reuse. Runs at the
// chip's achieved HBM ceiling of ~6.8 TB/s (85-86% of 8 TB/s spec for a
// 1:1 R/W mix). Identical-binary reruns (156.7/157.7/156.7 us) establish
// a ±0.5 us noise band; all flat-grid variants (vector width 128/256-bit,
// block 128/256/512, grid 16k/32k, .cs hints, FMA vs butterfly,
// 1 vs 2 positions/thread) are indistinguishable inside it. The only
// out-of-band variant was the persistent single-wave grid: -10% (fewer
// independent CTAs starves the L1tex/DRAM request pool).
// This configuration: 256-bit LDG/STG (two adjacent float4 slots per
// thread), 256-thread blocks, 16384 independent CTAs, default caching,
// FFMA-imm arithmetic.

#define N_  8u
#define H_  512u
#define W_  512u
#define C_  64u
#define HO  (H_/2u)       // 256
#define WO  (W_/2u)       // 256
#define C8  (C_/8u)       // 8 f8-groups per position
#define Q4  (N_*HO*WO*(C_/4u)) // float4 per quadrant = 8,388,608

struct __align__(32) f8 { float4 lo, hi; };

__device__ __forceinline__ f8 haar8(const f8& a, const f8& b,
                                    const f8& c, const f8& d,
                                    float sa, float sb, float sc)
{
    f8 r;
    r.lo.x = 0.5f * (sa*a.lo.x + sb*b.lo.x + sc*c.lo.x + d.lo.x);
    r.lo.y = 0.5f * (sa*a.lo.y + sb*b.lo.y + sc*c.lo.y + d.lo.y);
    r.lo.z = 0.5f * (sa*a.lo.z + sb*b.lo.z + sc*c.lo.z + d.lo.z);
    r.lo.w = 0.5f * (sa*a.lo.w + sb*b.lo.w + sc*c.lo.w + d.lo.w);
    r.hi.x = 0.5f * (sa*a.hi.x + sb*b.hi.x + sc*c.hi.x + d.hi.x);
    r.hi.y = 0.5f * (sa*a.hi.y + sb*b.hi.y + sc*c.hi.y + d.hi.y);
    r.hi.z = 0.5f * (sa*a.hi.z + sb*b.hi.z + sc*c.hi.z + d.hi.z);
    r.hi.w = 0.5f * (sa*a.hi.w + sb*b.hi.w + sc*c.hi.w + d.hi.w);
    return r;
}

__global__ __launch_bounds__(256) void wavelet_pool_kernel(
    const f8* __restrict__ in, f8* __restrict__ out)
{
    unsigned tid = blockIdx.x * blockDim.x + threadIdx.x;
    // tid -> (n, ho, wo, c8): c8 in [0,8), wo in [0,256), ho in [0,256), n in [0,8)
    unsigned c8 = tid & 7u;
    unsigned wo = (tid >> 3) & 255u;
    unsigned ho = (tid >> 11) & 255u;
    unsigned n  = tid >> 19;

    // input f8 index: ((n*H + 2*ho)*W + 2*wo)*C8 + c8
    unsigned ibase = ((n * H_ + 2u * ho) * W_ + 2u * wo) * C8 + c8;
    const unsigned ROW8 = W_ * C8;  // f8 per input row = 4096

    f8 a = in[ibase];
    f8 b = in[ibase + C8];
    f8 c = in[ibase + ROW8];
    f8 d = in[ibase + ROW8 + C8];

    f8 ll = haar8(a, b, c, d,  1.f,  1.f,  1.f);
    f8 lh = haar8(a, b, c, d, -1.f,  1.f, -1.f);
    f8 hl = haar8(a, b, c, d, -1.f, -1.f,  1.f);
    f8 hh = haar8(a, b, c, d,  1.f, -1.f, -1.f);

    const unsigned Q8 = Q4 / 2u;  // f8 per quadrant = 4,194,304
    unsigned o = ((n * HO + ho) * WO + wo) * C8 + c8;
    out[o]          = ll;
    out[o + Q8]     = lh;
    out[o + 2u*Q8]  = hl;
    out[o + 3u*Q8]  = hh;
}

extern "C" void kernel_launch(void* const* d_in, const int* in_sizes, int n_in,
                              void* d_out, int out_size)
{
    const f8* in  = (const f8*)d_in[0];
    f8*       out = (f8*)d_out;

    const unsigned total = Q4 / 2u;        // 4,194,304 threads
    const unsigned block = 256;
    const unsigned grid  = total / block;  // 16384
    wavelet_pool_kernel<<<grid, block>>>(in, out);
}

// round 13
// speedup vs baseline: 1.0002x; 1.0002x over previous
#include <cuda_runtime.h>

// WaveLetPooling: input (8, 512, 512, 64) fp32 NHWC.
// a = in[:,0::2,0::2,:], b = in[:,0::2,1::2,:], c = in[:,1::2,0::2,:], d = in[:,1::2,1::2,:]
// ll = .5(a+b+c+d); lh = .5(-a+b-c+d); hl = .5(-a-b+c+d); hh = .5(a-b-c+d)
// Output: [ll | lh | hl | hh], each (8, 256, 256, 64), concatenated in d_out.
//
// FINAL — roofline-converged (12-round sweep, session closed).
// Pure streaming op: 537 MB read + 537 MB write, zero reuse, provably
// minimal traffic. Pinned at the chip's achieved HBM ceiling of
// ~6.8 TB/s (85-86% of 8 TB/s spec for a 1:1 R/W mix). Four
// identical-binary runs: 156.7/157.7/156.7/157.6 us (sigma ~0.5 us).
// All flat-grid variants (vector width 128/256-bit, block 128/256/512,
// grid 16k/32k, .cs hints, FMA vs butterfly, 1 vs 2 positions/thread)
// are indistinguishable inside the noise band; the persistent
// single-wave grid was -10% (starves the memory request pool); TMA is
// bounded by the same path-independent LTS cap. The residual 15% to
// spec is memory-controller R/W turnaround — not SASS-addressable.
// Configuration: 256-bit LDG/STG (two adjacent float4 slots per thread),
// 256-thread blocks, 16384 independent CTAs, default caching, FFMA-imm.

#define N_  8u
#define H_  512u
#define W_  512u
#define C_  64u
#define HO  (H_/2u)       // 256
#define WO  (W_/2u)       // 256
#define C8  (C_/8u)       // 8 f8-groups per position
#define Q4  (N_*HO*WO*(C_/4u)) // float4 per quadrant = 8,388,608

struct __align__(32) f8 { float4 lo, hi; };

__device__ __forceinline__ f8 haar8(const f8& a, const f8& b,
                                    const f8& c, const f8& d,
                                    float sa, float sb, float sc)
{
    f8 r;
    r.lo.x = 0.5f * (sa*a.lo.x + sb*b.lo.x + sc*c.lo.x + d.lo.x);
    r.lo.y = 0.5f * (sa*a.lo.y + sb*b.lo.y + sc*c.lo.y + d.lo.y);
    r.lo.z = 0.5f * (sa*a.lo.z + sb*b.lo.z + sc*c.lo.z + d.lo.z);
    r.lo.w = 0.5f * (sa*a.lo.w + sb*b.lo.w + sc*c.lo.w + d.lo.w);
    r.hi.x = 0.5f * (sa*a.hi.x + sb*b.hi.x + sc*c.hi.x + d.hi.x);
    r.hi.y = 0.5f * (sa*a.hi.y + sb*b.hi.y + sc*c.hi.y + d.hi.y);
    r.hi.z = 0.5f * (sa*a.hi.z + sb*b.hi.z + sc*c.hi.z + d.hi.z);
    r.hi.w = 0.5f * (sa*a.hi.w + sb*b.hi.w + sc*c.hi.w + d.hi.w);
    return r;
}

__global__ __launch_bounds__(256) void wavelet_pool_kernel(
    const f8* __restrict__ in, f8* __restrict__ out)
{
    unsigned tid = blockIdx.x * blockDim.x + threadIdx.x;
    // tid -> (n, ho, wo, c8): c8 in [0,8), wo in [0,256), ho in [0,256), n in [0,8)
    unsigned c8 = tid & 7u;
    unsigned wo = (tid >> 3) & 255u;
    unsigned ho = (tid >> 11) & 255u;
    unsigned n  = tid >> 19;

    // input f8 index: ((n*H + 2*ho)*W + 2*wo)*C8 + c8
    unsigned ibase = ((n * H_ + 2u * ho) * W_ + 2u * wo) * C8 + c8;
    const unsigned ROW8 = W_ * C8;  // f8 per input row = 4096

    f8 a = in[ibase];
    f8 b = in[ibase + C8];
    f8 c = in[ibase + ROW8];
    f8 d = in[ibase + ROW8 + C8];

    f8 ll = haar8(a, b, c, d,  1.f,  1.f,  1.f);
    f8 lh = haar8(a, b, c, d, -1.f,  1.f, -1.f);
    f8 hl = haar8(a, b, c, d, -1.f, -1.f,  1.f);
    f8 hh = haar8(a, b, c, d,  1.f, -1.f, -1.f);

    const unsigned Q8 = Q4 / 2u;  // f8 per quadrant = 4,194,304
    unsigned o = ((n * HO + ho) * WO + wo) * C8 + c8;
    out[o]          = ll;
    out[o + Q8]     = lh;
    out[o + 2u*Q8]  = hl;
    out[o + 3u*Q8]  = hh;
}

extern "C" void kernel_launch(void* const* d_in, const int* in_sizes, int n_in,
                              void* d_out, int out_size)
{
    const f8* in  = (const f8*)d_in[0];
    f8*       out = (f8*)d_out;

    const unsigned total = Q4 / 2u;        // 4,194,304 threads
    const unsigned block = 256;
    const unsigned grid  = total / block;  // 16384
    wavelet_pool_kernel<<<grid, block>>>(in, out);
}

// round 14
// speedup vs baseline: 1.0008x; 1.0006x over previous
#include <cuda_runtime.h>

// WaveLetPooling: input (8, 512, 512, 64) fp32 NHWC.
// a = in[:,0::2,0::2,:], b = in[:,0::2,1::2,:], c = in[:,1::2,0::2,:], d = in[:,1::2,1::2,:]
// ll = .5(a+b+c+d); lh = .5(-a+b-c+d); hl = .5(-a-b+c+d); hh = .5(a-b-c+d)
// Output: [ll | lh | hl | hh], each (8, 256, 256, 64), concatenated in d_out.
//
// FINAL — roofline-converged (13-round sweep, session closed).
// Pure streaming op: 537 MB read + 537 MB write, zero reuse, provably
// minimal traffic. Pinned at the chip's achieved HBM ceiling of
// ~6.8 TB/s (85-86% of 8 TB/s spec for a 1:1 R/W mix). Five
// identical-binary runs: 156.7/157.7/156.7/157.6/157.6 us (sigma ~0.5).
// All flat-grid variants (vector width 128/256-bit, block 128/256/512,
// grid 16k/32k, .cs hints, FMA vs butterfly, 1 vs 2 positions/thread)
// are indistinguishable inside the noise band; persistent single-wave
// grid was -10% (starves the memory request pool); TMA is bounded by
// the same path-independent LTS cap. The residual 15% to spec is
// memory-controller R/W turnaround — not SASS-addressable.
// Configuration: 256-bit LDG/STG (two adjacent float4 slots per thread),
// 256-thread blocks, 16384 independent CTAs, default caching, FFMA-imm.

#define N_  8u
#define H_  512u
#define W_  512u
#define C_  64u
#define HO  (H_/2u)       // 256
#define WO  (W_/2u)       // 256
#define C8  (C_/8u)       // 8 f8-groups per position
#define Q4  (N_*HO*WO*(C_/4u)) // float4 per quadrant = 8,388,608

struct __align__(32) f8 { float4 lo, hi; };

__device__ __forceinline__ f8 haar8(const f8& a, const f8& b,
                                    const f8& c, const f8& d,
                                    float sa, float sb, float sc)
{
    f8 r;
    r.lo.x = 0.5f * (sa*a.lo.x + sb*b.lo.x + sc*c.lo.x + d.lo.x);
    r.lo.y = 0.5f * (sa*a.lo.y + sb*b.lo.y + sc*c.lo.y + d.lo.y);
    r.lo.z = 0.5f * (sa*a.lo.z + sb*b.lo.z + sc*c.lo.z + d.lo.z);
    r.lo.w = 0.5f * (sa*a.lo.w + sb*b.lo.w + sc*c.lo.w + d.lo.w);
    r.hi.x = 0.5f * (sa*a.hi.x + sb*b.hi.x + sc*c.hi.x + d.hi.x);
    r.hi.y = 0.5f * (sa*a.hi.y + sb*b.hi.y + sc*c.hi.y + d.hi.y);
    r.hi.z = 0.5f * (sa*a.hi.z + sb*b.hi.z + sc*c.hi.z + d.hi.z);
    r.hi.w = 0.5f * (sa*a.hi.w + sb*b.hi.w + sc*c.hi.w + d.hi.w);
    return r;
}

__global__ __launch_bounds__(256) void wavelet_pool_kernel(
    const f8* __restrict__ in, f8* __restrict__ out)
{
    unsigned tid = blockIdx.x * blockDim.x + threadIdx.x;
    // tid -> (n, ho, wo, c8): c8 in [0,8), wo in [0,256), ho in [0,256), n in [0,8)
    unsigned c8 = tid & 7u;
    unsigned wo = (tid >> 3) & 255u;
    unsigned ho = (tid >> 11) & 255u;
    unsigned n  = tid >> 19;

    // input f8 index: ((n*H + 2*ho)*W + 2*wo)*C8 + c8
    unsigned ibase = ((n * H_ + 2u * ho) * W_ + 2u * wo) * C8 + c8;
    const unsigned ROW8 = W_ * C8;  // f8 per input row = 4096

    f8 a = in[ibase];
    f8 b = in[ibase + C8];
    f8 c = in[ibase + ROW8];
    f8 d = in[ibase + ROW8 + C8];

    f8 ll = haar8(a, b, c, d,  1.f,  1.f,  1.f);
    f8 lh = haar8(a, b, c, d, -1.f,  1.f, -1.f);
    f8 hl = haar8(a, b, c, d, -1.f, -1.f,  1.f);
    f8 hh = haar8(a, b, c, d,  1.f, -1.f, -1.f);

    const unsigned Q8 = Q4 / 2u;  // f8 per quadrant = 4,194,304
    unsigned o = ((n * HO + ho) * WO + wo) * C8 + c8;
    out[o]          = ll;
    out[o + Q8]     = lh;
    out[o + 2u*Q8]  = hl;
    out[o + 3u*Q8]  = hh;
}

extern "C" void kernel_launch(void* const* d_in, const int* in_sizes, int n_in,
                              void* d_out, int out_size)
{
    const f8* in  = (const f8*)d_in[0];
    f8*       out = (f8*)d_out;

    const unsigned total = Q4 / 2u;        // 4,194,304 threads
    const unsigned block = 256;
    const unsigned grid  = total / block;  // 16384
    wavelet_pool_kernel<<<grid, block>>>(in, out);
}

// round 15
// speedup vs baseline: 1.0092x; 1.0084x over previous
#include <cuda_runtime.h>

// WaveLetPooling: input (8, 512, 512, 64) fp32 NHWC.
// a = in[:,0::2,0::2,:], b = in[:,0::2,1::2,:], c = in[:,1::2,0::2,:], d = in[:,1::2,1::2,:]
// ll = .5(a+b+c+d); lh = .5(-a+b-c+d); hl = .5(-a-b+c+d); hh = .5(a-b-c+d)
// Output: [ll | lh | hl | hh], each (8, 256, 256, 64), concatenated in d_out.
//
// FINAL — roofline-converged (14-round sweep, session closed).
// Pure streaming op: 537 MB read + 537 MB write, zero reuse, provably
// minimal traffic. Pinned at the chip's achieved HBM ceiling of
// ~6.8 TB/s (85-86% of 8 TB/s spec for a 1:1 R/W mix). Six
// identical-binary runs: 156.7/157.7/156.7/157.6/157.6/157.5 us
// (sigma ~0.5 us). All flat-grid variants (vector width 128/256-bit,
// block 128/256/512, grid 16k/32k, .cs hints, FMA vs butterfly,
// 1 vs 2 positions/thread) are indistinguishable inside the noise band;
// persistent single-wave grid was -10% (starves the memory request
// pool); TMA is bounded by the same path-independent LTS cap. The
// residual 15% to spec is memory-controller R/W turnaround — not
// SASS-addressable.
// Configuration: 256-bit LDG/STG (two adjacent float4 slots per thread),
// 256-thread blocks, 16384 independent CTAs, default caching, FFMA-imm.

#define N_  8u
#define H_  512u
#define W_  512u
#define C_  64u
#define HO  (H_/2u)       // 256
#define WO  (W_/2u)       // 256
#define C8  (C_/8u)       // 8 f8-groups per position
#define Q4  (N_*HO*WO*(C_/4u)) // float4 per quadrant = 8,388,608

struct __align__(32) f8 { float4 lo, hi; };

__device__ __forceinline__ f8 haar8(const f8& a, const f8& b,
                                    const f8& c, const f8& d,
                                    float sa, float sb, float sc)
{
    f8 r;
    r.lo.x = 0.5f * (sa*a.lo.x + sb*b.lo.x + sc*c.lo.x + d.lo.x);
    r.lo.y = 0.5f * (sa*a.lo.y + sb*b.lo.y + sc*c.lo.y + d.lo.y);
    r.lo.z = 0.5f * (sa*a.lo.z + sb*b.lo.z + sc*c.lo.z + d.lo.z);
    r.lo.w = 0.5f * (sa*a.lo.w + sb*b.lo.w + sc*c.lo.w + d.lo.w);
    r.hi.x = 0.5f * (sa*a.hi.x + sb*b.hi.x + sc*c.hi.x + d.hi.x);
    r.hi.y = 0.5f * (sa*a.hi.y + sb*b.hi.y + sc*c.hi.y + d.hi.y);
    r.hi.z = 0.5f * (sa*a.hi.z + sb*b.hi.z + sc*c.hi.z + d.hi.z);
    r.hi.w = 0.5f * (sa*a.hi.w + sb*b.hi.w + sc*c.hi.w + d.hi.w);
    return r;
}

__global__ __launch_bounds__(256) void wavelet_pool_kernel(
    const f8* __restrict__ in, f8* __restrict__ out)
{
    unsigned tid = blockIdx.x * blockDim.x + threadIdx.x;
    // tid -> (n, ho, wo, c8): c8 in [0,8), wo in [0,256), ho in [0,256), n in [0,8)
    unsigned c8 = tid & 7u;
    unsigned wo = (tid >> 3) & 255u;
    unsigned ho = (tid >> 11) & 255u;
    unsigned n  = tid >> 19;

    // input f8 index: ((n*H + 2*ho)*W + 2*wo)*C8 + c8
    unsigned ibase = ((n * H_ + 2u * ho) * W_ + 2u * wo) * C8 + c8;
    const unsigned ROW8 = W_ * C8;  // f8 per input row = 4096

    f8 a = in[ibase];
    f8 b = in[ibase + C8];
    f8 c = in[ibase + ROW8];
    f8 d = in[ibase + ROW8 + C8];

    f8 ll = haar8(a, b, c, d,  1.f,  1.f,  1.f);
    f8 lh = haar8(a, b, c, d, -1.f,  1.f, -1.f);
    f8 hl = haar8(a, b, c, d, -1.f, -1.f,  1.f);
    f8 hh = haar8(a, b, c, d,  1.f, -1.f, -1.f);

    const unsigned Q8 = Q4 / 2u;  // f8 per quadrant = 4,194,304
    unsigned o = ((n * HO + ho) * WO + wo) * C8 + c8;
    out[o]          = ll;
    out[o + Q8]     = lh;
    out[o + 2u*Q8]  = hl;
    out[o + 3u*Q8]  = hh;
}

extern "C" void kernel_launch(void* const* d_in, const int* in_sizes, int n_in,
                              void* d_out, int out_size)
{
    const f8* in  = (const f8*)d_in[0];
    f8*       out = (f8*)d_out;

    const unsigned total = Q4 / 2u;        // 4,194,304 threads
    const unsigned block = 256;
    const unsigned grid  = total / block;  // 16384
    wavelet_pool_kernel<<<grid, block>>>(in, out);
}